// round 3
// baseline (speedup 1.0000x reference)
#include <cuda_runtime.h>

#define HID 128
#define NRAD 6
#define NNODES 100000
#define LDSH 129   // padded leading dim for shared tiles (conflict-free frags)

// Node accumulator scratch (static __device__: allocation-free per harness rules)
__device__ float g_node[(size_t)NNODES * HID];
__device__ int g_idx_is64;   // 1 if index buffer is int64, 0 if int32

// ---------------------------------------------------------------------------
// Detect index dtype: int64 little-endian with values < 2^31 has zero odd
// 32-bit words; int32 node ids are random in [0, 100000). Deterministic.
// ---------------------------------------------------------------------------
__global__ void detect_idx_kernel(const int* __restrict__ idx32) {
    if (threadIdx.x == 0 && blockIdx.x == 0) {
        int all_zero = 1;
#pragma unroll
        for (int k = 1; k <= 31; k += 2) all_zero &= (idx32[k] == 0);
        g_idx_is64 = all_zero;
    }
}

// ---------------------------------------------------------------------------
// Zero the node accumulator
// ---------------------------------------------------------------------------
__global__ void zero_node_kernel() {
    size_t i = (size_t)blockIdx.x * blockDim.x + threadIdx.x;
    const size_t n4 = (size_t)NNODES * HID / 4;
    if (i < n4)
        reinterpret_cast<float4*>(g_node)[i] = make_float4(0.f, 0.f, 0.f, 0.f);
}

// ---------------------------------------------------------------------------
// Phase 1: gated = (rbf @ W_rbf^T) * x ; scatter-add into g_node[i[e]]
// One warp per edge (grid-stride). Lane l owns h = 4*l .. 4*l+3.
// Gate weights (24 floats per lane) hoisted into registers once per warp.
// Scatter via vector reduction red.global.add.v4.f32 (sm_90+).
// ---------------------------------------------------------------------------
__global__ void edge_scatter_kernel(const float* __restrict__ x,
                                    const float* __restrict__ rbf,
                                    const void* __restrict__ idx,
                                    const float* __restrict__ Wrbf,
                                    int E) {
    const int lane = threadIdx.x & 31;
    const int wglobal = (blockIdx.x * blockDim.x + threadIdx.x) >> 5;
    const int nwarps  = (gridDim.x * blockDim.x) >> 5;
    const int h0 = lane * 4;
    const int is64 = g_idx_is64;
    const int*       idx32 = (const int*)idx;
    const long long* idx64 = (const long long*)idx;

    // Per-lane gate weight block W_rbf[h0+j][r], j=0..3, r=0..5 (registers)
    float w[4][NRAD];
#pragma unroll
    for (int j = 0; j < 4; j++)
#pragma unroll
        for (int r = 0; r < NRAD; r++)
            w[j][r] = __ldg(&Wrbf[(h0 + j) * NRAD + r]);

    for (int e = wglobal; e < E; e += nwarps) {
        const float2* rb2 = reinterpret_cast<const float2*>(rbf + (size_t)e * NRAD);
        float2 ra  = __ldg(rb2 + 0);
        float2 rbv = __ldg(rb2 + 1);
        float2 rc  = __ldg(rb2 + 2);
        float r0 = ra.x, r1 = ra.y, r2 = rbv.x, r3 = rbv.y, r4 = rc.x, r5 = rc.y;

        float4 xv = *reinterpret_cast<const float4*>(x + (size_t)e * HID + h0);

        float g0 = w[0][0]*r0 + w[0][1]*r1 + w[0][2]*r2 + w[0][3]*r3 + w[0][4]*r4 + w[0][5]*r5;
        float g1 = w[1][0]*r0 + w[1][1]*r1 + w[1][2]*r2 + w[1][3]*r3 + w[1][4]*r4 + w[1][5]*r5;
        float g2 = w[2][0]*r0 + w[2][1]*r1 + w[2][2]*r2 + w[2][3]*r3 + w[2][4]*r4 + w[2][5]*r5;
        float g3 = w[3][0]*r0 + w[3][1]*r1 + w[3][2]*r2 + w[3][3]*r3 + w[3][4]*r4 + w[3][5]*r5;

        float v0 = g0 * xv.x, v1 = g1 * xv.y, v2 = g2 * xv.z, v3 = g3 * xv.w;

        long long node = is64 ? __ldg(&idx64[e]) : (long long)__ldg(&idx32[e]);
        if ((unsigned long long)node >= (unsigned long long)NNODES) continue;  // defensive

        float* dst = g_node + (size_t)node * HID + h0;  // 16B aligned (h0 % 4 == 0)
        asm volatile("red.global.add.v4.f32 [%0], {%1, %2, %3, %4};"
                     :: "l"(dst), "f"(v0), "f"(v1), "f"(v2), "f"(v3)
                     : "memory");
    }
}

// ---------------------------------------------------------------------------
// Phase 2: fused 4-layer MLP over node features.
// One CTA = 128 rows. h tile lives in SMEM across all 4 layers; weights are
// staged per layer. 256 threads, each computes an 8x8 microtile with strided
// (x16) row/col fragments -> conflict-free LDS with LDSH=129 padding.
// ---------------------------------------------------------------------------
__global__ void mlp_kernel(const float* __restrict__ W1, const float* __restrict__ b1,
                           const float* __restrict__ W2, const float* __restrict__ b2,
                           const float* __restrict__ W3, const float* __restrict__ b3,
                           const float* __restrict__ Wout,
                           float* __restrict__ out, int nrows) {
    extern __shared__ float smem[];
    float* sH = smem;              // [128][LDSH]
    float* sW = smem + HID * LDSH; // [128][LDSH]

    const int tid = threadIdx.x;     // 256 threads
    const int tx = tid & 15;         // col group
    const int ty = tid >> 4;         // row group
    const int row0 = blockIdx.x * HID;

    // Load h tile (guard partial last tile with zeros)
    for (int q = tid; q < HID * (HID / 4); q += blockDim.x) {
        int r = q >> 5;
        int c = (q & 31) << 2;
        float4 v = make_float4(0.f, 0.f, 0.f, 0.f);
        if (row0 + r < nrows)
            v = *reinterpret_cast<const float4*>(g_node + (size_t)(row0 + r) * HID + c);
        float* p = sH + r * LDSH + c;
        p[0] = v.x; p[1] = v.y; p[2] = v.z; p[3] = v.w;
    }

    const float* Ws[4] = {W1, W2, W3, Wout};
    const float* Bs[3] = {b1, b2, b3};

    for (int layer = 0; layer < 4; layer++) {
        __syncthreads();
        // Stage this layer's weights [o][k] row-major into sW
        const float* W = Ws[layer];
        for (int q = tid; q < HID * (HID / 4); q += blockDim.x) {
            int r = q >> 5;
            int c = (q & 31) << 2;
            float4 v = *reinterpret_cast<const float4*>(W + r * HID + c);
            float* p = sW + r * LDSH + c;
            p[0] = v.x; p[1] = v.y; p[2] = v.z; p[3] = v.w;
        }
        __syncthreads();

        float acc[8][8];
#pragma unroll
        for (int j = 0; j < 8; j++)
#pragma unroll
            for (int i2 = 0; i2 < 8; i2++) acc[j][i2] = 0.f;

#pragma unroll 4
        for (int k = 0; k < HID; k++) {
            float a[8], b[8];
#pragma unroll
            for (int j = 0; j < 8; j++)  a[j]  = sH[(ty + j * 16) * LDSH + k];
#pragma unroll
            for (int i2 = 0; i2 < 8; i2++) b[i2] = sW[(tx + i2 * 16) * LDSH + k];
#pragma unroll
            for (int j = 0; j < 8; j++)
#pragma unroll
                for (int i2 = 0; i2 < 8; i2++)
                    acc[j][i2] += a[j] * b[i2];
        }
        __syncthreads();  // all reads of sH/sW done before overwrite

        if (layer < 3) {
            float bias[8];
#pragma unroll
            for (int i2 = 0; i2 < 8; i2++) bias[i2] = __ldg(&Bs[layer][tx + i2 * 16]);
#pragma unroll
            for (int j = 0; j < 8; j++) {
#pragma unroll
                for (int i2 = 0; i2 < 8; i2++) {
                    float v = acc[j][i2] + bias[i2];
                    v = v / (1.f + __expf(-v));   // silu
                    sH[(ty + j * 16) * LDSH + (tx + i2 * 16)] = v;
                }
            }
        } else {
            // Final projection: write to global output
#pragma unroll
            for (int j = 0; j < 8; j++) {
                int r = row0 + ty + j * 16;
                if (r < nrows) {
#pragma unroll
                    for (int i2 = 0; i2 < 8; i2++)
                        out[(size_t)r * HID + (tx + i2 * 16)] = acc[j][i2];
                }
            }
        }
    }
}

// ---------------------------------------------------------------------------
// Launch
// ---------------------------------------------------------------------------
extern "C" void kernel_launch(void* const* d_in, const int* in_sizes, int n_in,
                              void* d_out, int out_size) {
    const float* x    = (const float*)d_in[0];
    const float* rbf  = (const float*)d_in[1];
    const void*  idx  = d_in[2];
    const float* Wrbf = (const float*)d_in[3];
    const float* W1   = (const float*)d_in[4];
    const float* b1   = (const float*)d_in[5];
    const float* W2   = (const float*)d_in[6];
    const float* b2   = (const float*)d_in[7];
    const float* W3   = (const float*)d_in[8];
    const float* b3   = (const float*)d_in[9];
    const float* Wout = (const float*)d_in[10];

    const int E     = in_sizes[0] / HID;
    const int nrows = out_size / HID;

    detect_idx_kernel<<<1, 32>>>((const int*)idx);

    const int n4 = NNODES * HID / 4;
    zero_node_kernel<<<(n4 + 255) / 256, 256>>>();

    edge_scatter_kernel<<<3552, 256>>>(x, rbf, idx, Wrbf, E);

    const size_t smem = (size_t)2 * HID * LDSH * sizeof(float);  // 132096 B
    cudaFuncSetAttribute(mlp_kernel, cudaFuncAttributeMaxDynamicSharedMemorySize, (int)smem);
    mlp_kernel<<<(nrows + HID - 1) / HID, 256, smem>>>(
        W1, b1, W2, b2, W3, b3, Wout, (float*)d_out, nrows);
}

// round 5
// speedup vs baseline: 1.1716x; 1.1716x over previous
#include <cuda_runtime.h>
#include <cuda_bf16.h>
#include <cstdint>

#define HID 128
#define NRAD 6
#define NNODES 100000
#define LDW 68        // B smem leading dim in 32-bit words (136 bf16)

// Node accumulator scratch (static __device__: allocation-free per harness rules)
__device__ float g_node[(size_t)NNODES * HID];
__device__ int g_idx_is64;   // 1 if index buffer is int64, 0 if int32

// ---------------------------------------------------------------------------
// Detect index dtype (int64 LE with small values has zero odd 32-bit words)
// ---------------------------------------------------------------------------
__global__ void detect_idx_kernel(const int* __restrict__ idx32) {
    if (threadIdx.x == 0 && blockIdx.x == 0) {
        int all_zero = 1;
#pragma unroll
        for (int k = 1; k <= 31; k += 2) all_zero &= (idx32[k] == 0);
        g_idx_is64 = all_zero;
    }
}

__global__ void zero_node_kernel() {
    size_t i = (size_t)blockIdx.x * blockDim.x + threadIdx.x;
    const size_t n4 = (size_t)NNODES * HID / 4;
    if (i < n4)
        reinterpret_cast<float4*>(g_node)[i] = make_float4(0.f, 0.f, 0.f, 0.f);
}

// ---------------------------------------------------------------------------
// Phase 1: gated = (rbf @ W_rbf^T) * x ; scatter-add via red.global.add.v4.f32
// ---------------------------------------------------------------------------
__global__ void edge_scatter_kernel(const float* __restrict__ x,
                                    const float* __restrict__ rbf,
                                    const void* __restrict__ idx,
                                    const float* __restrict__ Wrbf,
                                    int E) {
    const int lane = threadIdx.x & 31;
    const int wglobal = (blockIdx.x * blockDim.x + threadIdx.x) >> 5;
    const int nwarps  = (gridDim.x * blockDim.x) >> 5;
    const int h0 = lane * 4;
    const int is64 = g_idx_is64;
    const int*       idx32 = (const int*)idx;
    const long long* idx64 = (const long long*)idx;

    float w[4][NRAD];
#pragma unroll
    for (int j = 0; j < 4; j++)
#pragma unroll
        for (int r = 0; r < NRAD; r++)
            w[j][r] = __ldg(&Wrbf[(h0 + j) * NRAD + r]);

    for (int e = wglobal; e < E; e += nwarps) {
        const float2* rb2 = reinterpret_cast<const float2*>(rbf + (size_t)e * NRAD);
        float2 ra  = __ldg(rb2 + 0);
        float2 rbv = __ldg(rb2 + 1);
        float2 rc  = __ldg(rb2 + 2);
        float r0 = ra.x, r1 = ra.y, r2 = rbv.x, r3 = rbv.y, r4 = rc.x, r5 = rc.y;

        float4 xv = *reinterpret_cast<const float4*>(x + (size_t)e * HID + h0);

        float g0 = w[0][0]*r0 + w[0][1]*r1 + w[0][2]*r2 + w[0][3]*r3 + w[0][4]*r4 + w[0][5]*r5;
        float g1 = w[1][0]*r0 + w[1][1]*r1 + w[1][2]*r2 + w[1][3]*r3 + w[1][4]*r4 + w[1][5]*r5;
        float g2 = w[2][0]*r0 + w[2][1]*r1 + w[2][2]*r2 + w[2][3]*r3 + w[2][4]*r4 + w[2][5]*r5;
        float g3 = w[3][0]*r0 + w[3][1]*r1 + w[3][2]*r2 + w[3][3]*r3 + w[3][4]*r4 + w[3][5]*r5;

        float v0 = g0 * xv.x, v1 = g1 * xv.y, v2 = g2 * xv.z, v3 = g3 * xv.w;

        long long node = is64 ? __ldg(&idx64[e]) : (long long)__ldg(&idx32[e]);
        if ((unsigned long long)node >= (unsigned long long)NNODES) continue;

        float* dst = g_node + (size_t)node * HID + h0;
        asm volatile("red.global.add.v4.f32 [%0], {%1, %2, %3, %4};"
                     :: "l"(dst), "f"(v0), "f"(v1), "f"(v2), "f"(v3)
                     : "memory");
    }
}

// ===========================================================================
// Phase 2: fused 4-layer MLP via mma.sync (HMMA) with split-bf16 3-MMA.
// CTA = 128 rows; 8 warps x 16 rows. Activations live in registers as MMA
// A-fragments across all layers (D-frag layout == next A-frag layout).
// Weights staged per layer as hi/lo bf16 in SMEM [n][k], LD=136 bf16.
// ===========================================================================

// pack two fp32 into hi-bf16x2 and lo-bf16x2 (residual)
__device__ __forceinline__ void split2(float a, float b, uint32_t& hi, uint32_t& lo) {
    __nv_bfloat16 ah = __float2bfloat16(a), bh = __float2bfloat16(b);
    float ar = a - __bfloat162float(ah);
    float br = b - __bfloat162float(bh);
    __nv_bfloat162 h2 = __nv_bfloat162(ah, bh);   // .x = a (low half)
    __nv_bfloat162 l2 = __nv_bfloat162(__float2bfloat16(ar), __float2bfloat16(br));
    hi = *reinterpret_cast<uint32_t*>(&h2);
    lo = *reinterpret_cast<uint32_t*>(&l2);
}

__device__ __forceinline__ void mma16816(float* acc, const uint32_t* a,
                                         uint32_t b0, uint32_t b1) {
    asm volatile(
        "mma.sync.aligned.m16n8k16.row.col.f32.bf16.bf16.f32 "
        "{%0,%1,%2,%3}, {%4,%5,%6,%7}, {%8,%9}, {%0,%1,%2,%3};"
        : "+f"(acc[0]), "+f"(acc[1]), "+f"(acc[2]), "+f"(acc[3])
        : "r"(a[0]), "r"(a[1]), "r"(a[2]), "r"(a[3]), "r"(b0), "r"(b1));
}

__global__ void __launch_bounds__(256) mlp_mma_kernel(
    const float* __restrict__ W1, const float* __restrict__ b1,
    const float* __restrict__ W2, const float* __restrict__ b2,
    const float* __restrict__ W3, const float* __restrict__ b3,
    const float* __restrict__ Wout,
    float* __restrict__ out, int nrows)
{
    extern __shared__ uint32_t sw[];          // [2][128*LDW] u32
    uint32_t* s_bhi = sw;
    uint32_t* s_blo = sw + 128 * LDW;

    const int tid  = threadIdx.x;
    const int lane = tid & 31;
    const int wid  = tid >> 5;
    const int qr   = lane >> 2;   // 0..7
    const int qc   = lane & 3;    // 0..3
    const int row0 = blockIdx.x * HID;
    const int mA   = row0 + wid * 16 + qr;      // this thread's first output row
    const int mB   = mA + 8;                    // second output row

    // Register-resident A fragments: ahi/alo[kstep][4]
    uint32_t ahi[8][4], alo[8][4];

    // ---- Layer-0 A fragments straight from g_node (fp32 -> hi/lo bf16) ----
#pragma unroll
    for (int s = 0; s < 8; s++) {
        int c0 = 16 * s + 2 * qc;
        float2 vA0 = make_float2(0.f, 0.f), vB0 = vA0, vA1 = vA0, vB1 = vA0;
        if (mA < nrows) {
            vA0 = *reinterpret_cast<const float2*>(g_node + (size_t)mA * HID + c0);
            vA1 = *reinterpret_cast<const float2*>(g_node + (size_t)mA * HID + c0 + 8);
        }
        if (mB < nrows) {
            vB0 = *reinterpret_cast<const float2*>(g_node + (size_t)mB * HID + c0);
            vB1 = *reinterpret_cast<const float2*>(g_node + (size_t)mB * HID + c0 + 8);
        }
        split2(vA0.x, vA0.y, ahi[s][0], alo[s][0]);
        split2(vB0.x, vB0.y, ahi[s][1], alo[s][1]);
        split2(vA1.x, vA1.y, ahi[s][2], alo[s][2]);
        split2(vB1.x, vB1.y, ahi[s][3], alo[s][3]);
    }

    const float* Ws[4] = {W1, W2, W3, Wout};
    const float* Bs[3] = {b1, b2, b3};

    for (int layer = 0; layer < 4; layer++) {
        // ---- Stage weights: fp32 [n][k] -> hi/lo bf16 smem tiles ----
        const float* W = Ws[layer];
        for (int q = tid; q < HID * (HID / 2); q += 256) {
            int n = q >> 6;            // 0..127
            int kp = q & 63;           // word (pair) index 0..63
            float2 v = *reinterpret_cast<const float2*>(W + n * HID + 2 * kp);
            uint32_t hi, lo;
            split2(v.x, v.y, hi, lo);
            s_bhi[n * LDW + kp] = hi;
            s_blo[n * LDW + kp] = lo;
        }
        __syncthreads();

        // ---- MMA mainloop: 8 ksteps x 16 ntiles x 3 splits ----
        float acc[16][4];
#pragma unroll
        for (int t = 0; t < 16; t++)
#pragma unroll
            for (int j = 0; j < 4; j++) acc[t][j] = 0.f;

#pragma unroll
        for (int s = 0; s < 8; s++) {
#pragma unroll
            for (int t = 0; t < 16; t++) {
                int w0 = (t * 8 + qr) * LDW + 8 * s + qc;  // n row, k-low word
                uint32_t bh0 = s_bhi[w0];
                uint32_t bh1 = s_bhi[w0 + 4];
                uint32_t bl0 = s_blo[w0];
                uint32_t bl1 = s_blo[w0 + 4];
                mma16816(acc[t], ahi[s], bh0, bh1);
                mma16816(acc[t], ahi[s], bl0, bl1);
                mma16816(acc[t], alo[s], bh0, bh1);
            }
        }
        __syncthreads();   // done reading smem; safe to restage next layer

        // ---- Epilogue ----
        if (layer < 3) {
            const float* bias = Bs[layer];
#pragma unroll
            for (int t = 0; t < 16; t++) {
                int c0 = 8 * t + 2 * qc;
                float bb0 = __ldg(&bias[c0]);
                float bb1 = __ldg(&bias[c0 + 1]);
                float v0 = acc[t][0] + bb0;
                float v1 = acc[t][1] + bb1;
                float v2 = acc[t][2] + bb0;
                float v3 = acc[t][3] + bb1;
                v0 = v0 / (1.f + __expf(-v0));
                v1 = v1 / (1.f + __expf(-v1));
                v2 = v2 / (1.f + __expf(-v2));
                v3 = v3 / (1.f + __expf(-v3));
                int s = t >> 1;
                int i0 = (t & 1) * 2;
                split2(v0, v1, ahi[s][i0],     alo[s][i0]);
                split2(v2, v3, ahi[s][i0 + 1], alo[s][i0 + 1]);
            }
        } else {
#pragma unroll
            for (int t = 0; t < 16; t++) {
                int c0 = 8 * t + 2 * qc;
                if (mA < nrows)
                    *reinterpret_cast<float2*>(out + (size_t)mA * HID + c0) =
                        make_float2(acc[t][0], acc[t][1]);
                if (mB < nrows)
                    *reinterpret_cast<float2*>(out + (size_t)mB * HID + c0) =
                        make_float2(acc[t][2], acc[t][3]);
            }
        }
    }
}

// ---------------------------------------------------------------------------
// Launch
// ---------------------------------------------------------------------------
extern "C" void kernel_launch(void* const* d_in, const int* in_sizes, int n_in,
                              void* d_out, int out_size) {
    const float* x    = (const float*)d_in[0];
    const float* rbf  = (const float*)d_in[1];
    const void*  idx  = d_in[2];
    const float* Wrbf = (const float*)d_in[3];
    const float* W1   = (const float*)d_in[4];
    const float* b1   = (const float*)d_in[5];
    const float* W2   = (const float*)d_in[6];
    const float* b2   = (const float*)d_in[7];
    const float* W3   = (const float*)d_in[8];
    const float* b3   = (const float*)d_in[9];
    const float* Wout = (const float*)d_in[10];

    const int E     = in_sizes[0] / HID;
    const int nrows = out_size / HID;

    detect_idx_kernel<<<1, 32>>>((const int*)idx);

    const int n4 = NNODES * HID / 4;
    zero_node_kernel<<<(n4 + 255) / 256, 256>>>();

    edge_scatter_kernel<<<3552, 256>>>(x, rbf, idx, Wrbf, E);

    const int smem = 2 * 128 * LDW * 4;   // 69632 B
    cudaFuncSetAttribute(mlp_mma_kernel, cudaFuncAttributeMaxDynamicSharedMemorySize, smem);
    mlp_mma_kernel<<<(nrows + HID - 1) / HID, 256, smem>>>(
        W1, b1, W2, b2, W3, b3, Wout, (float*)d_out, nrows);
}

// round 6
// speedup vs baseline: 1.3444x; 1.1475x over previous
#include <cuda_runtime.h>
#include <cuda_bf16.h>
#include <cstdint>

#define HID 128
#define NRAD 6
#define NNODES 100000
#define LDW 68        // smem leading dim in 32-bit words (136 bf16)

// Node accumulator scratch (static __device__: allocation-free per harness rules)
__device__ float g_node[(size_t)NNODES * HID];
__device__ int g_idx_is64;   // 1 if index buffer is int64, 0 if int32

// ---------------------------------------------------------------------------
// Detect index dtype (int64 LE with small values has zero odd 32-bit words)
// ---------------------------------------------------------------------------
__global__ void detect_idx_kernel(const int* __restrict__ idx32) {
    if (threadIdx.x == 0 && blockIdx.x == 0) {
        int all_zero = 1;
#pragma unroll
        for (int k = 1; k <= 31; k += 2) all_zero &= (idx32[k] == 0);
        g_idx_is64 = all_zero;
    }
}

__global__ void zero_node_kernel() {
    size_t i = (size_t)blockIdx.x * blockDim.x + threadIdx.x;
    const size_t n4 = (size_t)NNODES * HID / 4;
    if (i < n4)
        reinterpret_cast<float4*>(g_node)[i] = make_float4(0.f, 0.f, 0.f, 0.f);
}

// ---------------------------------------------------------------------------
// Phase 1: gated = (rbf @ W_rbf^T) * x ; scatter-add via red.global.add.v4.f32
// (unchanged from R5 — known good)
// ---------------------------------------------------------------------------
__global__ void edge_scatter_kernel(const float* __restrict__ x,
                                    const float* __restrict__ rbf,
                                    const void* __restrict__ idx,
                                    const float* __restrict__ Wrbf,
                                    int E) {
    const int lane = threadIdx.x & 31;
    const int wglobal = (blockIdx.x * blockDim.x + threadIdx.x) >> 5;
    const int nwarps  = (gridDim.x * blockDim.x) >> 5;
    const int h0 = lane * 4;
    const int is64 = g_idx_is64;
    const int*       idx32 = (const int*)idx;
    const long long* idx64 = (const long long*)idx;

    float w[4][NRAD];
#pragma unroll
    for (int j = 0; j < 4; j++)
#pragma unroll
        for (int r = 0; r < NRAD; r++)
            w[j][r] = __ldg(&Wrbf[(h0 + j) * NRAD + r]);

    for (int e = wglobal; e < E; e += nwarps) {
        const float2* rb2 = reinterpret_cast<const float2*>(rbf + (size_t)e * NRAD);
        float2 ra  = __ldg(rb2 + 0);
        float2 rbv = __ldg(rb2 + 1);
        float2 rc  = __ldg(rb2 + 2);
        float r0 = ra.x, r1 = ra.y, r2 = rbv.x, r3 = rbv.y, r4 = rc.x, r5 = rc.y;

        float4 xv = *reinterpret_cast<const float4*>(x + (size_t)e * HID + h0);

        float g0 = w[0][0]*r0 + w[0][1]*r1 + w[0][2]*r2 + w[0][3]*r3 + w[0][4]*r4 + w[0][5]*r5;
        float g1 = w[1][0]*r0 + w[1][1]*r1 + w[1][2]*r2 + w[1][3]*r3 + w[1][4]*r4 + w[1][5]*r5;
        float g2 = w[2][0]*r0 + w[2][1]*r1 + w[2][2]*r2 + w[2][3]*r3 + w[2][4]*r4 + w[2][5]*r5;
        float g3 = w[3][0]*r0 + w[3][1]*r1 + w[3][2]*r2 + w[3][3]*r3 + w[3][4]*r4 + w[3][5]*r5;

        float v0 = g0 * xv.x, v1 = g1 * xv.y, v2 = g2 * xv.z, v3 = g3 * xv.w;

        long long node = is64 ? __ldg(&idx64[e]) : (long long)__ldg(&idx32[e]);
        if ((unsigned long long)node >= (unsigned long long)NNODES) continue;

        float* dst = g_node + (size_t)node * HID + h0;
        asm volatile("red.global.add.v4.f32 [%0], {%1, %2, %3, %4};"
                     :: "l"(dst), "f"(v0), "f"(v1), "f"(v2), "f"(v3)
                     : "memory");
    }
}

// ===========================================================================
// Phase 2: fused 4-layer MLP via mma.sync split-bf16 (3 MMAs per GEMM).
// 512 threads / 16 warps per CTA of 128 rows. Warp w: rows (w&7)*16,
// col half (w>>3)*64 -> acc is only 8 n-tiles (32 regs). Activations live in
// SMEM as hi/lo bf16 (LDW=68 words: conflict-free for frag LDS and STS).
// ===========================================================================

__device__ __forceinline__ void split2(float a, float b, uint32_t& hi, uint32_t& lo) {
    __nv_bfloat16 ah = __float2bfloat16(a), bh = __float2bfloat16(b);
    float ar = a - __bfloat162float(ah);
    float br = b - __bfloat162float(bh);
    __nv_bfloat162 h2 = __nv_bfloat162(ah, bh);   // .x = a (low half)
    __nv_bfloat162 l2 = __nv_bfloat162(__float2bfloat16(ar), __float2bfloat16(br));
    hi = *reinterpret_cast<uint32_t*>(&h2);
    lo = *reinterpret_cast<uint32_t*>(&l2);
}

__device__ __forceinline__ void mma16816(float* acc, const uint32_t* a,
                                         uint32_t b0, uint32_t b1) {
    asm volatile(
        "mma.sync.aligned.m16n8k16.row.col.f32.bf16.bf16.f32 "
        "{%0,%1,%2,%3}, {%4,%5,%6,%7}, {%8,%9}, {%0,%1,%2,%3};"
        : "+f"(acc[0]), "+f"(acc[1]), "+f"(acc[2]), "+f"(acc[3])
        : "r"(a[0]), "r"(a[1]), "r"(a[2]), "r"(a[3]), "r"(b0), "r"(b1));
}

#define TILE_WORDS (128 * LDW)   // 8704 u32 per tile

__global__ void __launch_bounds__(512) mlp_mma_kernel(
    const float* __restrict__ W1, const float* __restrict__ b1,
    const float* __restrict__ W2, const float* __restrict__ b2,
    const float* __restrict__ W3, const float* __restrict__ b3,
    const float* __restrict__ Wout,
    float* __restrict__ out, int nrows)
{
    extern __shared__ uint32_t sw[];
    uint32_t* s_bhi = sw;                      // weights hi
    uint32_t* s_blo = sw + TILE_WORDS;         // weights lo
    uint32_t* s_ahi = sw + 2 * TILE_WORDS;     // activations hi
    uint32_t* s_alo = sw + 3 * TILE_WORDS;     // activations lo

    const int tid  = threadIdx.x;
    const int lane = tid & 31;
    const int wid  = tid >> 5;                 // 0..15
    const int qr   = lane >> 2;                // 0..7
    const int qc   = lane & 3;                 // 0..3
    const int row0 = blockIdx.x * HID;
    const int rloc = (wid & 7) * 16;           // warp's local row base
    const int nh   = wid >> 3;                 // column half 0/1
    const int mAl  = rloc + qr;                // local output rows
    const int mBl  = mAl + 8;
    const int mA   = row0 + mAl;
    const int mB   = row0 + mBl;

    // ---- Stage layer-0 activations: g_node fp32 -> hi/lo bf16 smem ----
    for (int q = tid; q < HID * (HID / 2); q += 512) {
        int r  = q >> 6;            // 0..127
        int kp = q & 63;            // word index
        float2 v = make_float2(0.f, 0.f);
        if (row0 + r < nrows)
            v = *reinterpret_cast<const float2*>(g_node + (size_t)(row0 + r) * HID + 2 * kp);
        uint32_t hi, lo;
        split2(v.x, v.y, hi, lo);
        s_ahi[r * LDW + kp] = hi;
        s_alo[r * LDW + kp] = lo;
    }

    const float* Ws[4] = {W1, W2, W3, Wout};
    const float* Bs[3] = {b1, b2, b3};

    for (int layer = 0; layer < 4; layer++) {
        // ---- Stage weights ----
        const float* W = Ws[layer];
        for (int q = tid; q < HID * (HID / 2); q += 512) {
            int n  = q >> 6;
            int kp = q & 63;
            float2 v = *reinterpret_cast<const float2*>(W + n * HID + 2 * kp);
            uint32_t hi, lo;
            split2(v.x, v.y, hi, lo);
            s_bhi[n * LDW + kp] = hi;
            s_blo[n * LDW + kp] = lo;
        }
        __syncthreads();   // weights + activations visible

        // ---- MMA mainloop: 8 ksteps x 8 ntiles x 3 splits ----
        float acc[8][4];
#pragma unroll
        for (int t = 0; t < 8; t++)
#pragma unroll
            for (int j = 0; j < 4; j++) acc[t][j] = 0.f;

#pragma unroll
        for (int s = 0; s < 8; s++) {
            // A fragments for this kstep from smem
            int aw = mAl * LDW + 8 * s + qc;
            int bwr = mBl * LDW + 8 * s + qc;
            uint32_t ahi[4], alo[4];
            ahi[0] = s_ahi[aw];        alo[0] = s_alo[aw];
            ahi[1] = s_ahi[bwr];       alo[1] = s_alo[bwr];
            ahi[2] = s_ahi[aw + 4];    alo[2] = s_alo[aw + 4];
            ahi[3] = s_ahi[bwr + 4];   alo[3] = s_alo[bwr + 4];

            // prefetch B for t=0
            int w0 = (nh * 64 + qr) * LDW + 8 * s + qc;
            uint32_t bh0 = s_bhi[w0], bh1 = s_bhi[w0 + 4];
            uint32_t bl0 = s_blo[w0], bl1 = s_blo[w0 + 4];

#pragma unroll
            for (int t = 0; t < 8; t++) {
                uint32_t cbh0 = bh0, cbh1 = bh1, cbl0 = bl0, cbl1 = bl1;
                if (t < 7) {
                    int wn = (nh * 64 + (t + 1) * 8 + qr) * LDW + 8 * s + qc;
                    bh0 = s_bhi[wn]; bh1 = s_bhi[wn + 4];
                    bl0 = s_blo[wn]; bl1 = s_blo[wn + 4];
                }
                mma16816(acc[t], ahi, cbh0, cbh1);
                mma16816(acc[t], ahi, cbl0, cbl1);
                mma16816(acc[t], alo, cbh0, cbh1);
            }
        }
        __syncthreads();   // all smem reads done before epilogue overwrites act

        // ---- Epilogue ----
        if (layer < 3) {
            const float* bias = Bs[layer];
#pragma unroll
            for (int t = 0; t < 8; t++) {
                int c0 = nh * 64 + 8 * t + 2 * qc;
                float bb0 = __ldg(&bias[c0]);
                float bb1 = __ldg(&bias[c0 + 1]);
                float v0 = acc[t][0] + bb0;
                float v1 = acc[t][1] + bb1;
                float v2 = acc[t][2] + bb0;
                float v3 = acc[t][3] + bb1;
                v0 = v0 / (1.f + __expf(-v0));
                v1 = v1 / (1.f + __expf(-v1));
                v2 = v2 / (1.f + __expf(-v2));
                v3 = v3 / (1.f + __expf(-v3));
                uint32_t hA, lA, hB, lB;
                split2(v0, v1, hA, lA);
                split2(v2, v3, hB, lB);
                int wA = mAl * LDW + nh * 32 + 4 * t + qc;
                int wB = mBl * LDW + nh * 32 + 4 * t + qc;
                s_ahi[wA] = hA;  s_alo[wA] = lA;
                s_ahi[wB] = hB;  s_alo[wB] = lB;
            }
        } else {
#pragma unroll
            for (int t = 0; t < 8; t++) {
                int c0 = nh * 64 + 8 * t + 2 * qc;
                if (mA < nrows)
                    *reinterpret_cast<float2*>(out + (size_t)mA * HID + c0) =
                        make_float2(acc[t][0], acc[t][1]);
                if (mB < nrows)
                    *reinterpret_cast<float2*>(out + (size_t)mB * HID + c0) =
                        make_float2(acc[t][2], acc[t][3]);
            }
        }
        // next iteration's weight-staging __syncthreads orders act stores
        // before the next MMA loop's reads
    }
}

// ---------------------------------------------------------------------------
// Launch
// ---------------------------------------------------------------------------
extern "C" void kernel_launch(void* const* d_in, const int* in_sizes, int n_in,
                              void* d_out, int out_size) {
    const float* x    = (const float*)d_in[0];
    const float* rbf  = (const float*)d_in[1];
    const void*  idx  = d_in[2];
    const float* Wrbf = (const float*)d_in[3];
    const float* W1   = (const float*)d_in[4];
    const float* b1   = (const float*)d_in[5];
    const float* W2   = (const float*)d_in[6];
    const float* b2   = (const float*)d_in[7];
    const float* W3   = (const float*)d_in[8];
    const float* b3   = (const float*)d_in[9];
    const float* Wout = (const float*)d_in[10];

    const int E     = in_sizes[0] / HID;
    const int nrows = out_size / HID;

    detect_idx_kernel<<<1, 32>>>((const int*)idx);

    const int n4 = NNODES * HID / 4;
    zero_node_kernel<<<(n4 + 255) / 256, 256>>>();

    edge_scatter_kernel<<<3552, 256>>>(x, rbf, idx, Wrbf, E);

    const int smem = 4 * TILE_WORDS * 4;   // 139264 B
    cudaFuncSetAttribute(mlp_mma_kernel, cudaFuncAttributeMaxDynamicSharedMemorySize, smem);
    mlp_mma_kernel<<<(nrows + HID - 1) / HID, 512, smem>>>(
        W1, b1, W2, b2, W3, b3, Wout, (float*)d_out, nrows);
}